// round 11
// baseline (speedup 1.0000x reference)
#include <cuda_runtime.h>
#include <cstdint>

#define Bsz 128
#define Tsz 512
#define Isz 64
#define Hsz 256
#define Gsz 768   // 3*H

// ---- device scratch (no cudaMalloc allowed) --------------------------------
__device__ float    g_gx  [(size_t)Tsz * Bsz * Gsz];  // [t][b][768] gate preactivations
__device__ float    g_h1  [(size_t)Tsz * Bsz * Hsz];  // [t][b][256] layer-0 outputs
__device__ float    g_hbuf[2 * Bsz * Hsz];            // double-buffered hidden state
__device__ unsigned g_cnt [2 * Tsz * 16];             // per layer/step/batch-group barrier

// ---- zero hidden state (+ optionally barrier counters) ---------------------
__global__ void zero_state(int zero_cnt) {
    const int stride = gridDim.x * blockDim.x;
    const int i0 = blockIdx.x * blockDim.x + threadIdx.x;
    for (int i = i0; i < 2 * Bsz * Hsz; i += stride) g_hbuf[i] = 0.0f;
    if (zero_cnt)
        for (int i = i0; i < 2 * Tsz * 16; i += stride) g_cnt[i] = 0u;
}

// ---- tf32x3 tensor-core GEMM (NT): g_gx[m][n] = A(m,:)·W(n,:) + bias[n] ----
// mode 0: Arow(m)=x[(b*T+t)*I], m = t*128+b (bm=t, local row=b), K=64
// mode 1: Arow(m)=g_h1+m*256, K=256
// CTA tile 128x64, K-chunk 32; 8 warps (4m x 2n), warp tile 32x32.
// Register-prefetch pipeline: next chunk's LDGs issued before current MMAs.
// Split: v = hi + lo (tf32-rounded); D = Ah*Bh + Ah*Bl + Al*Bh.
#define GSTRIDE 36
#define GEMM_SMEM_FLOATS (128*GSTRIDE*2 + 64*GSTRIDE*2)
#define GEMM_SMEM_BYTES  (GEMM_SMEM_FLOATS * 4)   // 55296

__device__ __forceinline__ void tf32_split(float v, float& hi, float& lo) {
    unsigned hb, lb;
    asm("cvt.rna.tf32.f32 %0, %1;" : "=r"(hb) : "f"(v));
    float h = __uint_as_float(hb);
    float l = v - h;
    asm("cvt.rna.tf32.f32 %0, %1;" : "=r"(lb) : "f"(l));
    hi = h;
    lo = __uint_as_float(lb);
}

#define MMA_TF32(c, a, b)                                                     \
    asm volatile(                                                             \
        "mma.sync.aligned.m16n8k8.row.col.f32.tf32.tf32.f32 "                 \
        "{%0,%1,%2,%3},{%4,%5,%6,%7},{%8,%9},{%0,%1,%2,%3};"                  \
        : "+f"((c)[0]), "+f"((c)[1]), "+f"((c)[2]), "+f"((c)[3])              \
        : "r"((a)[0]), "r"((a)[1]), "r"((a)[2]), "r"((a)[3]),                 \
          "r"((b)[0]), "r"((b)[1]))

__global__ __launch_bounds__(256) void gemm_tf32(
    const float* __restrict__ A, const float* __restrict__ W,
    const float* __restrict__ bias, int K, int mode)
{
    extern __shared__ float gsm[];
    float* sAh = gsm;                         // [128][36]
    float* sAl = sAh + 128 * GSTRIDE;         // [128][36]
    float* sBh = sAl + 128 * GSTRIDE;         // [64][36]
    float* sBl = sBh + 64 * GSTRIDE;          // [64][36]

    const int tid  = threadIdx.x;
    const int warp = tid >> 5, lane = tid & 31;
    const int gr   = lane >> 2, tg = lane & 3;
    const int wm   = warp & 3,  wn = warp >> 2;
    const int bm   = blockIdx.y, bn = blockIdx.x;

    // per-thread staging coordinates (A: 4 f4, B: 2 f4)
    int arow[4], ac4[4], brow[2], bc4[2];
    const float* asrc[4];
    const float* bsrc[2];
#pragma unroll
    for (int i = 0; i < 4; ++i) {
        const int idx = tid + (i << 8);
        arow[i] = idx >> 3; ac4[i] = idx & 7;
        asrc[i] = (mode == 0)
            ? A    + ((size_t)arow[i] * Tsz + bm) * Isz + (ac4[i] << 2)
            : g_h1 + ((size_t)bm * 128 + arow[i]) * Hsz + (ac4[i] << 2);
    }
#pragma unroll
    for (int i = 0; i < 2; ++i) {
        const int idx = tid + (i << 8);
        brow[i] = idx >> 3; bc4[i] = idx & 7;
        bsrc[i] = W + ((size_t)(bn * 64 + brow[i])) * K + (bc4[i] << 2);
    }

    float c[2][4][4];
#pragma unroll
    for (int ms = 0; ms < 2; ++ms)
#pragma unroll
        for (int ns = 0; ns < 4; ++ns)
#pragma unroll
            for (int i = 0; i < 4; ++i) c[ms][ns][i] = 0.0f;

    // fragment base pointers (hoisted)
    const float* pAh[2];
    const float* pAl[2];
#pragma unroll
    for (int ms = 0; ms < 2; ++ms) {
        const int r0 = wm * 32 + ms * 16 + gr;
        pAh[ms] = sAh + r0 * GSTRIDE + tg;
        pAl[ms] = sAl + r0 * GSTRIDE + tg;
    }
    const float* pBh[4];
    const float* pBl[4];
#pragma unroll
    for (int ns = 0; ns < 4; ++ns) {
        const int n0 = wn * 32 + ns * 8 + gr;
        pBh[ns] = sBh + n0 * GSTRIDE + tg;
        pBl[ns] = sBl + n0 * GSTRIDE + tg;
    }

    // prefetch chunk 0
    float4 ra[4], rb[2];
#pragma unroll
    for (int i = 0; i < 4; ++i) ra[i] = __ldg((const float4*)asrc[i]);
#pragma unroll
    for (int i = 0; i < 2; ++i) rb[i] = __ldg((const float4*)bsrc[i]);

    for (int kc = 0; kc < K; kc += 32) {
        // split current regs -> smem
#pragma unroll
        for (int i = 0; i < 4; ++i) {
            float* dh = sAh + arow[i] * GSTRIDE + (ac4[i] << 2);
            float* dl = sAl + arow[i] * GSTRIDE + (ac4[i] << 2);
            tf32_split(ra[i].x, dh[0], dl[0]);
            tf32_split(ra[i].y, dh[1], dl[1]);
            tf32_split(ra[i].z, dh[2], dl[2]);
            tf32_split(ra[i].w, dh[3], dl[3]);
        }
#pragma unroll
        for (int i = 0; i < 2; ++i) {
            float* dh = sBh + brow[i] * GSTRIDE + (bc4[i] << 2);
            float* dl = sBl + brow[i] * GSTRIDE + (bc4[i] << 2);
            tf32_split(rb[i].x, dh[0], dl[0]);
            tf32_split(rb[i].y, dh[1], dl[1]);
            tf32_split(rb[i].z, dh[2], dl[2]);
            tf32_split(rb[i].w, dh[3], dl[3]);
        }
        __syncthreads();

        // issue next chunk's LDGs now; they retire under the MMAs below
        if (kc + 32 < K) {
#pragma unroll
            for (int i = 0; i < 4; ++i)
                ra[i] = __ldg((const float4*)(asrc[i] + kc + 32));
#pragma unroll
            for (int i = 0; i < 2; ++i)
                rb[i] = __ldg((const float4*)(bsrc[i] + kc + 32));
        }

#pragma unroll
        for (int ks = 0; ks < 4; ++ks) {
            const int k0 = ks << 3;
            unsigned Ah[2][4], Al[2][4];
#pragma unroll
            for (int ms = 0; ms < 2; ++ms) {
                const float* ph = pAh[ms] + k0;
                const float* pl = pAl[ms] + k0;
                Ah[ms][0] = __float_as_uint(ph[0]);
                Ah[ms][1] = __float_as_uint(ph[8 * GSTRIDE]);
                Ah[ms][2] = __float_as_uint(ph[4]);
                Ah[ms][3] = __float_as_uint(ph[8 * GSTRIDE + 4]);
                Al[ms][0] = __float_as_uint(pl[0]);
                Al[ms][1] = __float_as_uint(pl[8 * GSTRIDE]);
                Al[ms][2] = __float_as_uint(pl[4]);
                Al[ms][3] = __float_as_uint(pl[8 * GSTRIDE + 4]);
            }
            unsigned Bh[4][2], Bl[4][2];
#pragma unroll
            for (int ns = 0; ns < 4; ++ns) {
                const float* ph = pBh[ns] + k0;
                const float* pl = pBl[ns] + k0;
                Bh[ns][0] = __float_as_uint(ph[0]);
                Bh[ns][1] = __float_as_uint(ph[4]);
                Bl[ns][0] = __float_as_uint(pl[0]);
                Bl[ns][1] = __float_as_uint(pl[4]);
            }
            // term-outer ordering: 8 independent accumulators between
            // dependent reuses of the same c[ms][ns]
#pragma unroll
            for (int ms = 0; ms < 2; ++ms)
#pragma unroll
                for (int ns = 0; ns < 4; ++ns)
                    MMA_TF32(c[ms][ns], Ah[ms], Bh[ns]);
#pragma unroll
            for (int ms = 0; ms < 2; ++ms)
#pragma unroll
                for (int ns = 0; ns < 4; ++ns)
                    MMA_TF32(c[ms][ns], Ah[ms], Bl[ns]);
#pragma unroll
            for (int ms = 0; ms < 2; ++ms)
#pragma unroll
                for (int ns = 0; ns < 4; ++ns)
                    MMA_TF32(c[ms][ns], Al[ms], Bh[ns]);
        }
        __syncthreads();   // MMA readers done before next split-store
    }

    // epilogue: bias add + store
#pragma unroll
    for (int ms = 0; ms < 2; ++ms) {
#pragma unroll
        for (int ns = 0; ns < 4; ++ns) {
            const int col = bn * 64 + wn * 32 + ns * 8 + tg * 2;
            const float b0 = __ldg(bias + col);
            const float b1 = __ldg(bias + col + 1);
            const size_t m0 = (size_t)bm * 128 + wm * 32 + ms * 16 + gr;
            float2 v0 = make_float2(c[ms][ns][0] + b0, c[ms][ns][1] + b1);
            float2 v1 = make_float2(c[ms][ns][2] + b0, c[ms][ns][3] + b1);
            *(float2*)(g_gx + m0 * Gsz + col)       = v0;
            *(float2*)(g_gx + (m0 + 8) * Gsz + col) = v1;
        }
    }
}

// ---- persistent GRU scan (unchanged from R9) --------------------------------
__global__ __launch_bounds__(256, 1) void gru_scan(
    const float* __restrict__ Whh, const float* __restrict__ bhh,
    int layer, int write_ys)
{
    __shared__ float shT[256 * 9];      // h transposed: [k][b], row pad 9
    __shared__ float sp [8 * 96 * 9];   // partials: [kc][g(96)][b], row pad 9

    const int tid = threadIdx.x;
    const int bg  = blockIdx.x >> 3;    // 0..15
    const int hg  = blockIdx.x & 7;     // 0..7
    const int b0  = bg << 3, j0 = hg << 5;

    const int kc = tid >> 5;            // k-chunk 0..7
    const int gc = tid & 31;            // hidden unit 0..31
    const int bl = tid >> 5;            // epilogue batch 0..7
    const int ge = tid & 31;            // epilogue hidden unit

    float w[3][32];
#pragma unroll
    for (int gi = 0; gi < 3; ++gi) {
        const float* wrow = Whh + (size_t)(gi * 256 + j0 + gc) * 256 + (kc << 5);
#pragma unroll
        for (int q = 0; q < 8; ++q) {
            float4 v = __ldg((const float4*)wrow + q);
            w[gi][q*4+0] = v.x; w[gi][q*4+1] = v.y;
            w[gi][q*4+2] = v.z; w[gi][q*4+3] = v.w;
        }
    }
    const float bhr = bhh[j0 + ge];
    const float bhz = bhh[256 + j0 + ge];
    const float bhn = bhh[512 + j0 + ge];
    unsigned* cnt = g_cnt + layer * (Tsz * 16);

    const float* gxp = g_gx + (size_t)(b0 + bl) * Gsz + j0 + ge;
    const size_t gxstep = (size_t)128 * Gsz;
    float gxr = __ldcg(gxp);
    float gxz = __ldcg(gxp + 256);
    float gxn = __ldcg(gxp + 512);

    int cur = 0;
    for (int t = 0; t < Tsz; ++t) {
        if (t > 0) {
            const unsigned* c = cnt + ((t - 1) << 4) + bg;
            unsigned v;
            do {
                asm volatile("ld.acquire.gpu.global.u32 %0, [%1];"
                             : "=r"(v) : "l"(c) : "memory");
            } while (v < 8u);
        }
        {
            const float* hsrc = g_hbuf + cur * (Bsz * Hsz) + (b0 << 8);
#pragma unroll
            for (int r = 0; r < 2; ++r) {
                const int i = tid + (r << 8);
                const int bb = i >> 6, k4 = i & 63;
                float4 v = __ldcg((const float4*)(hsrc + (bb << 8)) + k4);
                float* d = shT + (k4 << 2) * 9 + bb;
                d[0] = v.x; d[9] = v.y; d[18] = v.z; d[27] = v.w;
            }
        }
        __syncthreads();

        float acc[3][8];
#pragma unroll
        for (int gi = 0; gi < 3; ++gi)
#pragma unroll
            for (int b = 0; b < 8; ++b) acc[gi][b] = 0.0f;

        const float* hk = shT + (kc << 5) * 9;
#pragma unroll
        for (int kk = 0; kk < 32; ++kk) {
            const float* hp = hk + kk * 9;
            float hh[8];
#pragma unroll
            for (int b = 0; b < 8; ++b) hh[b] = hp[b];
#pragma unroll
            for (int gi = 0; gi < 3; ++gi) {
                const float wv = w[gi][kk];
#pragma unroll
                for (int b = 0; b < 8; ++b)
                    acc[gi][b] = fmaf(wv, hh[b], acc[gi][b]);
            }
        }
#pragma unroll
        for (int gi = 0; gi < 3; ++gi)
#pragma unroll
            for (int b = 0; b < 8; ++b)
                sp[((kc * 96) + gi * 32 + gc) * 9 + b] = acc[gi][b];
        __syncthreads();

        float ar = bhr + gxr, az = bhz + gxz, an = bhn;
#pragma unroll
        for (int k8 = 0; k8 < 8; ++k8) {
            ar += sp[(k8 * 96 + ge) * 9 + bl];
            az += sp[(k8 * 96 + 32 + ge) * 9 + bl];
            an += sp[(k8 * 96 + 64 + ge) * 9 + bl];
        }
        const float r = __fdividef(1.0f, 1.0f + __expf(-ar));
        const float z = __fdividef(1.0f, 1.0f + __expf(-az));
        const float xn = fmaf(r, an, gxn);
        const float e = __expf(2.0f * fabsf(xn));
        float n = 1.0f - __fdividef(2.0f, e + 1.0f);
        n = copysignf(n, xn);

        const float hold = shT[(j0 + ge) * 9 + bl];
        const float hnew = fmaf(z, hold - n, n);

        __stcg(g_hbuf + (cur ^ 1) * (Bsz * Hsz) + ((b0 + bl) << 8) + j0 + ge, hnew);
        if (write_ys)
            g_h1[(size_t)((t << 7) + b0 + bl) * Hsz + j0 + ge] = hnew;

        if (t + 1 < Tsz) {
            const float* p = gxp + (size_t)(t + 1) * gxstep;
            gxr = __ldcg(p);
            gxz = __ldcg(p + 256);
            gxn = __ldcg(p + 512);
        }

        __syncthreads();
        if (t + 1 < Tsz && tid == 0) {
            asm volatile("red.release.gpu.global.add.u32 [%0], 1;"
                         :: "l"(cnt + (t << 4) + bg) : "memory");
        }
        cur ^= 1;
    }
}

// ---- head: out[b] = W2 . relu(W1 . h_last[b] + b1) + b2 --------------------
__global__ void head_kernel(const float* __restrict__ W1, const float* __restrict__ b1,
                            const float* __restrict__ W2, const float* __restrict__ b2,
                            float* __restrict__ out)
{
    __shared__ float red[128];
    const int b = blockIdx.x, u = threadIdx.x;
    const float* hb = g_hbuf + (b << 8);
    const float* w  = W1 + (size_t)u * 256;

    float acc = b1[u];
#pragma unroll 8
    for (int k4 = 0; k4 < 64; ++k4) {
        const float4 h4 = __ldcg((const float4*)hb + k4);
        const float4 w4 = __ldg((const float4*)w + k4);
        acc = fmaf(h4.x, w4.x, acc); acc = fmaf(h4.y, w4.y, acc);
        acc = fmaf(h4.z, w4.z, acc); acc = fmaf(h4.w, w4.w, acc);
    }
    red[u] = fmaxf(acc, 0.0f) * __ldg(W2 + u);
    __syncthreads();
#pragma unroll
    for (int s = 64; s > 0; s >>= 1) {
        if (u < s) red[u] += red[u + s];
        __syncthreads();
    }
    if (u == 0) out[b] = red[0] + b2[0];
}

// ---- launch sequence (graph-capturable: kernel launches only) --------------
extern "C" void kernel_launch(void* const* d_in, const int* in_sizes, int n_in,
                              void* d_out, int out_size)
{
    const float* x    = (const float*)d_in[0];
    const float* Wih0 = (const float*)d_in[1];
    const float* Whh0 = (const float*)d_in[2];
    const float* bih0 = (const float*)d_in[3];
    const float* bhh0 = (const float*)d_in[4];
    const float* Wih1 = (const float*)d_in[5];
    const float* Whh1 = (const float*)d_in[6];
    const float* bih1 = (const float*)d_in[7];
    const float* bhh1 = (const float*)d_in[8];
    const float* W1   = (const float*)d_in[9];
    const float* b1   = (const float*)d_in[10];
    const float* W2   = (const float*)d_in[11];
    const float* b2   = (const float*)d_in[12];
    float* out = (float*)d_out;

    cudaFuncSetAttribute(gemm_tf32, cudaFuncAttributeMaxDynamicSharedMemorySize,
                         GEMM_SMEM_BYTES);

    const dim3 ggrid(12, 512);   // 12 n-tiles of 64, 512 t-tiles of 128 rows

    // fresh state + barrier counters every replay
    zero_state<<<64, 256>>>(1);

    // layer 0
    gemm_tf32<<<ggrid, 256, GEMM_SMEM_BYTES>>>(x, Wih0, bih0, Isz, 0);
    gru_scan<<<128, 256>>>(Whh0, bhh0, 0, 1);

    // layer 1 (re-zero hidden state: layer 1 starts from h=0)
    gemm_tf32<<<ggrid, 256, GEMM_SMEM_BYTES>>>(x, Wih1, bih1, Hsz, 1);
    zero_state<<<64, 256>>>(0);
    gru_scan<<<128, 256>>>(Whh1, bhh1, 1, 0);

    // head
    head_kernel<<<128, 128>>>(W1, b1, W2, b2, out);
}

// round 12
// speedup vs baseline: 1.0496x; 1.0496x over previous
#include <cuda_runtime.h>
#include <cuda_bf16.h>
#include <cstdint>

#define Bsz 128
#define Tsz 512
#define Isz 64
#define Hsz 256
#define Gsz 768   // 3*H

// ---- device scratch (no cudaMalloc allowed) --------------------------------
__device__ float    g_gx  [(size_t)Tsz * Bsz * Gsz];  // [t][b][768] gate preactivations
__device__ float    g_h1  [(size_t)Tsz * Bsz * Hsz];  // [t][b][256] layer-0 outputs
__device__ float    g_hbuf[2 * Bsz * Hsz];            // double-buffered hidden state
__device__ unsigned g_cnt [2 * Tsz * 16];             // per layer/step/batch-group barrier

// ---- zero hidden state (+ optionally barrier counters) ---------------------
__global__ void zero_state(int zero_cnt) {
    const int stride = gridDim.x * blockDim.x;
    const int i0 = blockIdx.x * blockDim.x + threadIdx.x;
    for (int i = i0; i < 2 * Bsz * Hsz; i += stride) g_hbuf[i] = 0.0f;
    if (zero_cnt)
        for (int i = i0; i < 2 * Tsz * 16; i += stride) g_cnt[i] = 0u;
}

// ---- bf16x2-split tensor-core GEMM (NT): g_gx[m][n] = A(m,:)·W(n,:)+bias ---
// mode 0: Arow(m)=x[(b*T+t)*I], m = t*128+b (bm=t, local row=b), K=64
// mode 1: Arow(m)=g_h1+m*256, K=256
// CTA 128x64, K-chunk 32 (2 k16 steps); 8 warps (4m x 2n), warp tile 32x32.
// Split v = hi + lo (bf16-rounded); D = Ah*Bh + Ah*Bl + Al*Bh (err ~2^-18).
// smem rows padded to 12 uints (48B) -> ldmatrix + scalar B loads conflict-free.
#define AKU 12   // uints per row per k16-step (8 data + 4 pad)

__device__ __forceinline__ unsigned pack2bf(float f0, float f1, float& r0, float& r1) {
    __nv_bfloat16 h0 = __float2bfloat16(f0);
    __nv_bfloat16 h1 = __float2bfloat16(f1);
    r0 = f0 - __bfloat162float(h0);
    r1 = f1 - __bfloat162float(h1);
    return (unsigned)__bfloat16_as_ushort(h0) |
           ((unsigned)__bfloat16_as_ushort(h1) << 16);
}
__device__ __forceinline__ unsigned pack2bf_only(float f0, float f1) {
    __nv_bfloat16 h0 = __float2bfloat16(f0);
    __nv_bfloat16 h1 = __float2bfloat16(f1);
    return (unsigned)__bfloat16_as_ushort(h0) |
           ((unsigned)__bfloat16_as_ushort(h1) << 16);
}

#define LDSM_X4(r0, r1, r2, r3, addr)                                         \
    asm volatile("ldmatrix.sync.aligned.m8n8.x4.shared.b16 {%0,%1,%2,%3}, [%4];" \
        : "=r"(r0), "=r"(r1), "=r"(r2), "=r"(r3) : "r"(addr))

#define MMA_BF16(c, a, b)                                                     \
    asm volatile(                                                             \
        "mma.sync.aligned.m16n8k16.row.col.f32.bf16.bf16.f32 "                \
        "{%0,%1,%2,%3},{%4,%5,%6,%7},{%8,%9},{%0,%1,%2,%3};"                  \
        : "+f"((c)[0]), "+f"((c)[1]), "+f"((c)[2]), "+f"((c)[3])              \
        : "r"((a)[0]), "r"((a)[1]), "r"((a)[2]), "r"((a)[3]),                 \
          "r"((b)[0]), "r"((b)[1]))

__global__ __launch_bounds__(256) void gemm_bf16x2(
    const float* __restrict__ A, const float* __restrict__ W,
    const float* __restrict__ bias, int K, int mode)
{
    // layout (uints): sAh[2][128][12], sAl[..], sBh[2][64][12], sBl[..]
    __shared__ unsigned gsm[2*128*AKU*2 + 2*64*AKU*2];   // 9216 uints = 36864 B
    unsigned* sAh = gsm;
    unsigned* sAl = gsm + 2*128*AKU;
    unsigned* sBh = gsm + 4*128*AKU;
    unsigned* sBl = gsm + 4*128*AKU + 2*64*AKU;

    const int tid  = threadIdx.x;
    const int warp = tid >> 5, lane = tid & 31;
    const int gr   = lane >> 2, tg = lane & 3;
    const int wm   = warp & 3,  wn = warp >> 2;
    const int bm   = blockIdx.y, bn = blockIdx.x;

    // staging coords (A: 4 float4/thread, B: 2)
    int arow[4], ac4[4], brow[2], bc4[2];
    const float* asrc[4];
    const float* bsrc[2];
#pragma unroll
    for (int i = 0; i < 4; ++i) {
        const int idx = tid + (i << 8);
        arow[i] = idx >> 3; ac4[i] = idx & 7;
        asrc[i] = (mode == 0)
            ? A    + ((size_t)arow[i] * Tsz + bm) * Isz + (ac4[i] << 2)
            : g_h1 + ((size_t)bm * 128 + arow[i]) * Hsz + (ac4[i] << 2);
    }
#pragma unroll
    for (int i = 0; i < 2; ++i) {
        const int idx = tid + (i << 8);
        brow[i] = idx >> 3; bc4[i] = idx & 7;
        bsrc[i] = W + ((size_t)(bn * 64 + brow[i])) * K + (bc4[i] << 2);
    }

    float c[2][4][4];
#pragma unroll
    for (int ms = 0; ms < 2; ++ms)
#pragma unroll
        for (int ns = 0; ns < 4; ++ns)
#pragma unroll
            for (int i = 0; i < 4; ++i) c[ms][ns][i] = 0.0f;

    // ldmatrix lane address components (A): row = lane&15, khalf = lane>>4
    const int lrow = lane & 15, lkh = lane >> 4;
    unsigned aAh = (unsigned)__cvta_generic_to_shared(sAh);
    unsigned aAl = (unsigned)__cvta_generic_to_shared(sAl);

    // prefetch chunk 0
    float4 ra[4], rb[2];
#pragma unroll
    for (int i = 0; i < 4; ++i) ra[i] = __ldg((const float4*)asrc[i]);
#pragma unroll
    for (int i = 0; i < 2; ++i) rb[i] = __ldg((const float4*)bsrc[i]);

    for (int kc = 0; kc < K; kc += 32) {
        // split current regs -> smem (bf16 hi plane + bf16 residual plane)
#pragma unroll
        for (int i = 0; i < 4; ++i) {
            const int ks = ac4[i] >> 2, pc = (ac4[i] & 3) << 1;
            const int di = ((ks << 7) + arow[i]) * AKU + pc;
            float r0, r1, r2, r3;
            unsigned h0 = pack2bf(ra[i].x, ra[i].y, r0, r1);
            unsigned h1 = pack2bf(ra[i].z, ra[i].w, r2, r3);
            sAh[di]     = h0; sAh[di + 1] = h1;
            sAl[di]     = pack2bf_only(r0, r1);
            sAl[di + 1] = pack2bf_only(r2, r3);
        }
#pragma unroll
        for (int i = 0; i < 2; ++i) {
            const int ks = bc4[i] >> 2, pc = (bc4[i] & 3) << 1;
            const int di = ((ks << 6) + brow[i]) * AKU + pc;
            float r0, r1, r2, r3;
            unsigned h0 = pack2bf(rb[i].x, rb[i].y, r0, r1);
            unsigned h1 = pack2bf(rb[i].z, rb[i].w, r2, r3);
            sBh[di]     = h0; sBh[di + 1] = h1;
            sBl[di]     = pack2bf_only(r0, r1);
            sBl[di + 1] = pack2bf_only(r2, r3);
        }
        __syncthreads();

        // issue next chunk's LDGs; retire under MMAs
        if (kc + 32 < K) {
#pragma unroll
            for (int i = 0; i < 4; ++i)
                ra[i] = __ldg((const float4*)(asrc[i] + kc + 32));
#pragma unroll
            for (int i = 0; i < 2; ++i)
                rb[i] = __ldg((const float4*)(bsrc[i] + kc + 32));
        }

#pragma unroll
        for (int ks = 0; ks < 2; ++ks) {
            // A fragments via ldmatrix.x4 (r0..r3 = a0..a3)
            unsigned Ah[2][4], Al[2][4];
#pragma unroll
            for (int ms = 0; ms < 2; ++ms) {
                const int rbase = wm * 32 + ms * 16;
                const unsigned off =
                    ((unsigned)(((ks << 7) + rbase + lrow) * AKU + (lkh << 2))) << 2;
                LDSM_X4(Ah[ms][0], Ah[ms][1], Ah[ms][2], Ah[ms][3], aAh + off);
                LDSM_X4(Al[ms][0], Al[ms][1], Al[ms][2], Al[ms][3], aAl + off);
            }
            // B fragments: scalar uint loads (conflict-free)
            unsigned Bh[4][2], Bl[4][2];
#pragma unroll
            for (int ns = 0; ns < 4; ++ns) {
                const int nrow = wn * 32 + ns * 8 + gr;
                const int di = ((ks << 6) + nrow) * AKU;
                Bh[ns][0] = sBh[di + tg];
                Bh[ns][1] = sBh[di + 4 + tg];
                Bl[ns][0] = sBl[di + tg];
                Bl[ns][1] = sBl[di + 4 + tg];
            }
            // 3 terms, term-outer (8 independent accumulators between reuses)
#pragma unroll
            for (int ms = 0; ms < 2; ++ms)
#pragma unroll
                for (int ns = 0; ns < 4; ++ns)
                    MMA_BF16(c[ms][ns], Ah[ms], Bh[ns]);
#pragma unroll
            for (int ms = 0; ms < 2; ++ms)
#pragma unroll
                for (int ns = 0; ns < 4; ++ns)
                    MMA_BF16(c[ms][ns], Ah[ms], Bl[ns]);
#pragma unroll
            for (int ms = 0; ms < 2; ++ms)
#pragma unroll
                for (int ns = 0; ns < 4; ++ns)
                    MMA_BF16(c[ms][ns], Al[ms], Bh[ns]);
        }
        __syncthreads();
    }

    // epilogue: bias add + store (c layout identical to m16n8k8 case)
#pragma unroll
    for (int ms = 0; ms < 2; ++ms) {
#pragma unroll
        for (int ns = 0; ns < 4; ++ns) {
            const int col = bn * 64 + wn * 32 + ns * 8 + tg * 2;
            const float b0 = __ldg(bias + col);
            const float b1 = __ldg(bias + col + 1);
            const size_t m0 = (size_t)bm * 128 + wm * 32 + ms * 16 + gr;
            float2 v0 = make_float2(c[ms][ns][0] + b0, c[ms][ns][1] + b1);
            float2 v1 = make_float2(c[ms][ns][2] + b0, c[ms][ns][3] + b1);
            *(float2*)(g_gx + m0 * Gsz + col)       = v0;
            *(float2*)(g_gx + (m0 + 8) * Gsz + col) = v1;
        }
    }
}

// ---- persistent GRU scan (unchanged from R9) --------------------------------
__global__ __launch_bounds__(256, 1) void gru_scan(
    const float* __restrict__ Whh, const float* __restrict__ bhh,
    int layer, int write_ys)
{
    __shared__ float shT[256 * 9];      // h transposed: [k][b], row pad 9
    __shared__ float sp [8 * 96 * 9];   // partials: [kc][g(96)][b], row pad 9

    const int tid = threadIdx.x;
    const int bg  = blockIdx.x >> 3;    // 0..15
    const int hg  = blockIdx.x & 7;     // 0..7
    const int b0  = bg << 3, j0 = hg << 5;

    const int kc = tid >> 5;            // k-chunk 0..7
    const int gc = tid & 31;            // hidden unit 0..31
    const int bl = tid >> 5;            // epilogue batch 0..7
    const int ge = tid & 31;            // epilogue hidden unit

    float w[3][32];
#pragma unroll
    for (int gi = 0; gi < 3; ++gi) {
        const float* wrow = Whh + (size_t)(gi * 256 + j0 + gc) * 256 + (kc << 5);
#pragma unroll
        for (int q = 0; q < 8; ++q) {
            float4 v = __ldg((const float4*)wrow + q);
            w[gi][q*4+0] = v.x; w[gi][q*4+1] = v.y;
            w[gi][q*4+2] = v.z; w[gi][q*4+3] = v.w;
        }
    }
    const float bhr = bhh[j0 + ge];
    const float bhz = bhh[256 + j0 + ge];
    const float bhn = bhh[512 + j0 + ge];
    unsigned* cnt = g_cnt + layer * (Tsz * 16);

    const float* gxp = g_gx + (size_t)(b0 + bl) * Gsz + j0 + ge;
    const size_t gxstep = (size_t)128 * Gsz;
    float gxr = __ldcg(gxp);
    float gxz = __ldcg(gxp + 256);
    float gxn = __ldcg(gxp + 512);

    int cur = 0;
    for (int t = 0; t < Tsz; ++t) {
        if (t > 0) {
            const unsigned* c = cnt + ((t - 1) << 4) + bg;
            unsigned v;
            do {
                asm volatile("ld.acquire.gpu.global.u32 %0, [%1];"
                             : "=r"(v) : "l"(c) : "memory");
            } while (v < 8u);
        }
        {
            const float* hsrc = g_hbuf + cur * (Bsz * Hsz) + (b0 << 8);
#pragma unroll
            for (int r = 0; r < 2; ++r) {
                const int i = tid + (r << 8);
                const int bb = i >> 6, k4 = i & 63;
                float4 v = __ldcg((const float4*)(hsrc + (bb << 8)) + k4);
                float* d = shT + (k4 << 2) * 9 + bb;
                d[0] = v.x; d[9] = v.y; d[18] = v.z; d[27] = v.w;
            }
        }
        __syncthreads();

        float acc[3][8];
#pragma unroll
        for (int gi = 0; gi < 3; ++gi)
#pragma unroll
            for (int b = 0; b < 8; ++b) acc[gi][b] = 0.0f;

        const float* hk = shT + (kc << 5) * 9;
#pragma unroll
        for (int kk = 0; kk < 32; ++kk) {
            const float* hp = hk + kk * 9;
            float hh[8];
#pragma unroll
            for (int b = 0; b < 8; ++b) hh[b] = hp[b];
#pragma unroll
            for (int gi = 0; gi < 3; ++gi) {
                const float wv = w[gi][kk];
#pragma unroll
                for (int b = 0; b < 8; ++b)
                    acc[gi][b] = fmaf(wv, hh[b], acc[gi][b]);
            }
        }
#pragma unroll
        for (int gi = 0; gi < 3; ++gi)
#pragma unroll
            for (int b = 0; b < 8; ++b)
                sp[((kc * 96) + gi * 32 + gc) * 9 + b] = acc[gi][b];
        __syncthreads();

        float ar = bhr + gxr, az = bhz + gxz, an = bhn;
#pragma unroll
        for (int k8 = 0; k8 < 8; ++k8) {
            ar += sp[(k8 * 96 + ge) * 9 + bl];
            az += sp[(k8 * 96 + 32 + ge) * 9 + bl];
            an += sp[(k8 * 96 + 64 + ge) * 9 + bl];
        }
        const float r = __fdividef(1.0f, 1.0f + __expf(-ar));
        const float z = __fdividef(1.0f, 1.0f + __expf(-az));
        const float xn = fmaf(r, an, gxn);
        const float e = __expf(2.0f * fabsf(xn));
        float n = 1.0f - __fdividef(2.0f, e + 1.0f);
        n = copysignf(n, xn);

        const float hold = shT[(j0 + ge) * 9 + bl];
        const float hnew = fmaf(z, hold - n, n);

        __stcg(g_hbuf + (cur ^ 1) * (Bsz * Hsz) + ((b0 + bl) << 8) + j0 + ge, hnew);
        if (write_ys)
            g_h1[(size_t)((t << 7) + b0 + bl) * Hsz + j0 + ge] = hnew;

        if (t + 1 < Tsz) {
            const float* p = gxp + (size_t)(t + 1) * gxstep;
            gxr = __ldcg(p);
            gxz = __ldcg(p + 256);
            gxn = __ldcg(p + 512);
        }

        __syncthreads();
        if (t + 1 < Tsz && tid == 0) {
            asm volatile("red.release.gpu.global.add.u32 [%0], 1;"
                         :: "l"(cnt + (t << 4) + bg) : "memory");
        }
        cur ^= 1;
    }
}

// ---- head: out[b] = W2 . relu(W1 . h_last[b] + b1) + b2 --------------------
__global__ void head_kernel(const float* __restrict__ W1, const float* __restrict__ b1,
                            const float* __restrict__ W2, const float* __restrict__ b2,
                            float* __restrict__ out)
{
    __shared__ float red[128];
    const int b = blockIdx.x, u = threadIdx.x;
    const float* hb = g_hbuf + (b << 8);
    const float* w  = W1 + (size_t)u * 256;

    float acc = b1[u];
#pragma unroll 8
    for (int k4 = 0; k4 < 64; ++k4) {
        const float4 h4 = __ldcg((const float4*)hb + k4);
        const float4 w4 = __ldg((const float4*)w + k4);
        acc = fmaf(h4.x, w4.x, acc); acc = fmaf(h4.y, w4.y, acc);
        acc = fmaf(h4.z, w4.z, acc); acc = fmaf(h4.w, w4.w, acc);
    }
    red[u] = fmaxf(acc, 0.0f) * __ldg(W2 + u);
    __syncthreads();
#pragma unroll
    for (int s = 64; s > 0; s >>= 1) {
        if (u < s) red[u] += red[u + s];
        __syncthreads();
    }
    if (u == 0) out[b] = red[0] + b2[0];
}

// ---- launch sequence (graph-capturable: kernel launches only) --------------
extern "C" void kernel_launch(void* const* d_in, const int* in_sizes, int n_in,
                              void* d_out, int out_size)
{
    const float* x    = (const float*)d_in[0];
    const float* Wih0 = (const float*)d_in[1];
    const float* Whh0 = (const float*)d_in[2];
    const float* bih0 = (const float*)d_in[3];
    const float* bhh0 = (const float*)d_in[4];
    const float* Wih1 = (const float*)d_in[5];
    const float* Whh1 = (const float*)d_in[6];
    const float* bih1 = (const float*)d_in[7];
    const float* bhh1 = (const float*)d_in[8];
    const float* W1   = (const float*)d_in[9];
    const float* b1   = (const float*)d_in[10];
    const float* W2   = (const float*)d_in[11];
    const float* b2   = (const float*)d_in[12];
    float* out = (float*)d_out;

    const dim3 ggrid(12, 512);   // 12 n-tiles of 64, 512 t-tiles of 128 rows

    // fresh state + barrier counters every replay
    zero_state<<<64, 256>>>(1);

    // layer 0
    gemm_bf16x2<<<ggrid, 256>>>(x, Wih0, bih0, Isz, 0);
    gru_scan<<<128, 256>>>(Whh0, bhh0, 0, 1);

    // layer 1 (re-zero hidden state: layer 1 starts from h=0)
    gemm_bf16x2<<<ggrid, 256>>>(x, Wih1, bih1, Hsz, 1);
    zero_state<<<64, 256>>>(0);
    gru_scan<<<128, 256>>>(Whh1, bhh1, 1, 0);

    // head
    head_kernel<<<128, 128>>>(W1, b1, W2, b2, out);
}

// round 13
// speedup vs baseline: 1.0634x; 1.0131x over previous
#include <cuda_runtime.h>
#include <cuda_bf16.h>
#include <cstdint>

#define Bsz 128
#define Tsz 512
#define Isz 64
#define Hsz 256
#define Gsz 768   // 3*H

// ---- device scratch (no cudaMalloc allowed) --------------------------------
__device__ float    g_gx  [(size_t)Tsz * Bsz * Gsz];  // [t][b][768] gate preactivations
__device__ float    g_h1  [(size_t)Tsz * Bsz * Hsz];  // [t][b][256] layer-0 outputs
__device__ float    g_hbuf[2 * Bsz * Hsz];            // double-buffered hidden state
__device__ unsigned g_cnt [2 * Tsz * 8];              // per layer/step/batch-group barrier

// ---- zero hidden state (+ optionally barrier counters) ---------------------
__global__ void zero_state(int zero_cnt) {
    const int stride = gridDim.x * blockDim.x;
    const int i0 = blockIdx.x * blockDim.x + threadIdx.x;
    for (int i = i0; i < 2 * Bsz * Hsz; i += stride) g_hbuf[i] = 0.0f;
    if (zero_cnt)
        for (int i = i0; i < 2 * Tsz * 8; i += stride) g_cnt[i] = 0u;
}

// ---- shared helpers: bf16 split + mma/ldmatrix -----------------------------
#define AKU 12   // uints per 16-row block row (8 data + 4 pad) -> LDSM conflict-free

__device__ __forceinline__ unsigned pack2bf(float f0, float f1, float& r0, float& r1) {
    __nv_bfloat16 h0 = __float2bfloat16(f0);
    __nv_bfloat16 h1 = __float2bfloat16(f1);
    r0 = f0 - __bfloat162float(h0);
    r1 = f1 - __bfloat162float(h1);
    return (unsigned)__bfloat16_as_ushort(h0) |
           ((unsigned)__bfloat16_as_ushort(h1) << 16);
}
__device__ __forceinline__ unsigned pack2bf_only(float f0, float f1) {
    __nv_bfloat16 h0 = __float2bfloat16(f0);
    __nv_bfloat16 h1 = __float2bfloat16(f1);
    return (unsigned)__bfloat16_as_ushort(h0) |
           ((unsigned)__bfloat16_as_ushort(h1) << 16);
}

#define LDSM_X4(r0, r1, r2, r3, addr)                                         \
    asm volatile("ldmatrix.sync.aligned.m8n8.x4.shared.b16 {%0,%1,%2,%3}, [%4];" \
        : "=r"(r0), "=r"(r1), "=r"(r2), "=r"(r3) : "r"(addr))

#define MMA_BF16(c, a, b)                                                     \
    asm volatile(                                                             \
        "mma.sync.aligned.m16n8k16.row.col.f32.bf16.bf16.f32 "                \
        "{%0,%1,%2,%3},{%4,%5,%6,%7},{%8,%9},{%0,%1,%2,%3};"                  \
        : "+f"((c)[0]), "+f"((c)[1]), "+f"((c)[2]), "+f"((c)[3])              \
        : "r"((a)[0]), "r"((a)[1]), "r"((a)[2]), "r"((a)[3]),                 \
          "r"((b)[0]), "r"((b)[1]))

// ---- bf16x2-split tensor-core GEMM (NT) — unchanged from R12 ---------------
__global__ __launch_bounds__(256) void gemm_bf16x2(
    const float* __restrict__ A, const float* __restrict__ W,
    const float* __restrict__ bias, int K, int mode)
{
    __shared__ unsigned gsm[2*128*AKU*2 + 2*64*AKU*2];
    unsigned* sAh = gsm;
    unsigned* sAl = gsm + 2*128*AKU;
    unsigned* sBh = gsm + 4*128*AKU;
    unsigned* sBl = gsm + 4*128*AKU + 2*64*AKU;

    const int tid  = threadIdx.x;
    const int warp = tid >> 5, lane = tid & 31;
    const int gr   = lane >> 2, tg = lane & 3;
    const int wm   = warp & 3,  wn = warp >> 2;
    const int bm   = blockIdx.y, bn = blockIdx.x;

    int arow[4], ac4[4], brow[2], bc4[2];
    const float* asrc[4];
    const float* bsrc[2];
#pragma unroll
    for (int i = 0; i < 4; ++i) {
        const int idx = tid + (i << 8);
        arow[i] = idx >> 3; ac4[i] = idx & 7;
        asrc[i] = (mode == 0)
            ? A    + ((size_t)arow[i] * Tsz + bm) * Isz + (ac4[i] << 2)
            : g_h1 + ((size_t)bm * 128 + arow[i]) * Hsz + (ac4[i] << 2);
    }
#pragma unroll
    for (int i = 0; i < 2; ++i) {
        const int idx = tid + (i << 8);
        brow[i] = idx >> 3; bc4[i] = idx & 7;
        bsrc[i] = W + ((size_t)(bn * 64 + brow[i])) * K + (bc4[i] << 2);
    }

    float c[2][4][4];
#pragma unroll
    for (int ms = 0; ms < 2; ++ms)
#pragma unroll
        for (int ns = 0; ns < 4; ++ns)
#pragma unroll
            for (int i = 0; i < 4; ++i) c[ms][ns][i] = 0.0f;

    const int lrow = lane & 15, lkh = lane >> 4;
    unsigned aAh = (unsigned)__cvta_generic_to_shared(sAh);
    unsigned aAl = (unsigned)__cvta_generic_to_shared(sAl);

    float4 ra[4], rb[2];
#pragma unroll
    for (int i = 0; i < 4; ++i) ra[i] = __ldg((const float4*)asrc[i]);
#pragma unroll
    for (int i = 0; i < 2; ++i) rb[i] = __ldg((const float4*)bsrc[i]);

    for (int kc = 0; kc < K; kc += 32) {
#pragma unroll
        for (int i = 0; i < 4; ++i) {
            const int ks = ac4[i] >> 2, pc = (ac4[i] & 3) << 1;
            const int di = ((ks << 7) + arow[i]) * AKU + pc;
            float r0, r1, r2, r3;
            unsigned h0 = pack2bf(ra[i].x, ra[i].y, r0, r1);
            unsigned h1 = pack2bf(ra[i].z, ra[i].w, r2, r3);
            sAh[di]     = h0; sAh[di + 1] = h1;
            sAl[di]     = pack2bf_only(r0, r1);
            sAl[di + 1] = pack2bf_only(r2, r3);
        }
#pragma unroll
        for (int i = 0; i < 2; ++i) {
            const int ks = bc4[i] >> 2, pc = (bc4[i] & 3) << 1;
            const int di = ((ks << 6) + brow[i]) * AKU + pc;
            float r0, r1, r2, r3;
            unsigned h0 = pack2bf(rb[i].x, rb[i].y, r0, r1);
            unsigned h1 = pack2bf(rb[i].z, rb[i].w, r2, r3);
            sBh[di]     = h0; sBh[di + 1] = h1;
            sBl[di]     = pack2bf_only(r0, r1);
            sBl[di + 1] = pack2bf_only(r2, r3);
        }
        __syncthreads();

        if (kc + 32 < K) {
#pragma unroll
            for (int i = 0; i < 4; ++i)
                ra[i] = __ldg((const float4*)(asrc[i] + kc + 32));
#pragma unroll
            for (int i = 0; i < 2; ++i)
                rb[i] = __ldg((const float4*)(bsrc[i] + kc + 32));
        }

#pragma unroll
        for (int ks = 0; ks < 2; ++ks) {
            unsigned Ah[2][4], Al[2][4];
#pragma unroll
            for (int ms = 0; ms < 2; ++ms) {
                const int rbase = wm * 32 + ms * 16;
                const unsigned off =
                    ((unsigned)(((ks << 7) + rbase + lrow) * AKU + (lkh << 2))) << 2;
                LDSM_X4(Ah[ms][0], Ah[ms][1], Ah[ms][2], Ah[ms][3], aAh + off);
                LDSM_X4(Al[ms][0], Al[ms][1], Al[ms][2], Al[ms][3], aAl + off);
            }
            unsigned Bh[4][2], Bl[4][2];
#pragma unroll
            for (int ns = 0; ns < 4; ++ns) {
                const int nrow = wn * 32 + ns * 8 + gr;
                const int di = ((ks << 6) + nrow) * AKU;
                Bh[ns][0] = sBh[di + tg];
                Bh[ns][1] = sBh[di + 4 + tg];
                Bl[ns][0] = sBl[di + tg];
                Bl[ns][1] = sBl[di + 4 + tg];
            }
#pragma unroll
            for (int ms = 0; ms < 2; ++ms)
#pragma unroll
                for (int ns = 0; ns < 4; ++ns)
                    MMA_BF16(c[ms][ns], Ah[ms], Bh[ns]);
#pragma unroll
            for (int ms = 0; ms < 2; ++ms)
#pragma unroll
                for (int ns = 0; ns < 4; ++ns)
                    MMA_BF16(c[ms][ns], Ah[ms], Bl[ns]);
#pragma unroll
            for (int ms = 0; ms < 2; ++ms)
#pragma unroll
                for (int ns = 0; ns < 4; ++ns)
                    MMA_BF16(c[ms][ns], Al[ms], Bh[ns]);
        }
        __syncthreads();
    }

#pragma unroll
    for (int ms = 0; ms < 2; ++ms) {
#pragma unroll
        for (int ns = 0; ns < 4; ++ns) {
            const int col = bn * 64 + wn * 32 + ns * 8 + tg * 2;
            const float b0 = __ldg(bias + col);
            const float b1 = __ldg(bias + col + 1);
            const size_t m0 = (size_t)bm * 128 + wm * 32 + ms * 16 + gr;
            float2 v0 = make_float2(c[ms][ns][0] + b0, c[ms][ns][1] + b1);
            float2 v1 = make_float2(c[ms][ns][2] + b0, c[ms][ns][3] + b1);
            *(float2*)(g_gx + m0 * Gsz + col)       = v0;
            *(float2*)(g_gx + (m0 + 8) * Gsz + col) = v1;
        }
    }
}

// ---- tensor-core GRU scan ----------------------------------------------------
// 128 CTAs = 8 bg x 16 hg; CTA tile: 16 batch x 16 hidden x 3 gates.
// m=16 (batch), n=48 (3 gates x 16 j), k=256. Warp w owns k-chunk [32w,32w+32).
// B (weights) split bf16 hi/lo held in REGISTERS for all 512 steps.
// A (h) staged each step into ldmatrix-layout bf16 hi/lo smem planes.
// 3-term split MMA: Ah*Bh + Ah*Bl + Al*Bh; fp32 partial reduce across warps.
#define SP_STRIDE 49
#define SCAN2_WORDS (2*16*16*AKU + 8*16*SP_STRIDE + 16*17)
#define SCAN2_BYTES (SCAN2_WORDS * 4)   // 50752

__global__ __launch_bounds__(256, 1) void gru_scan_mma(
    const float* __restrict__ Whh, const float* __restrict__ bhh,
    int layer, int write_ys)
{
    extern __shared__ unsigned smu[];
    unsigned* sAh = smu;                         // [16 ks][16 row][12]
    unsigned* sAl = smu + 16*16*AKU;
    float* sp     = (float*)(smu + 2*16*16*AKU); // [8 warp][16 m][49]
    float* sHold  = sp + 8*16*SP_STRIDE;         // [16][17] f32 h tile

    const int tid  = threadIdx.x;
    const int warp = tid >> 5, lane = tid & 31;
    const int gr   = lane >> 2, tg = lane & 3;
    const int bg   = blockIdx.x >> 4;            // 0..7
    const int hg   = blockIdx.x & 15;            // 0..15
    const int b0   = bg << 4, j0 = hg << 4;
    const int bl   = tid >> 4;                   // epilogue batch 0..15
    const int jl   = tid & 15;                   // epilogue hidden 0..15

    // B fragments (weights) -> registers, once. Warp k-chunk = [warp*32, +32).
    unsigned Bh[2][6][2], Bl[2][6][2];
#pragma unroll
    for (int s = 0; s < 2; ++s) {
#pragma unroll
        for (int ns = 0; ns < 6; ++ns) {
            const int n = ns * 8 + gr;                       // 0..47
            const int g = n >> 4, jj = n & 15;
            const float* wr = Whh + (size_t)(g * 256 + j0 + jj) * 256;
            const int k0 = warp * 32 + s * 16 + tg * 2;
            float r0, r1;
            Bh[s][ns][0] = pack2bf(wr[k0],     wr[k0 + 1], r0, r1);
            Bl[s][ns][0] = pack2bf_only(r0, r1);
            Bh[s][ns][1] = pack2bf(wr[k0 + 8], wr[k0 + 9], r0, r1);
            Bl[s][ns][1] = pack2bf_only(r0, r1);
        }
    }
    const float bhr = bhh[j0 + jl];
    const float bhz = bhh[256 + j0 + jl];
    const float bhn = bhh[512 + j0 + jl];
    unsigned* cnt = g_cnt + layer * (Tsz * 8);

    // gx prefetch (one (b,j) per thread, 3 gates)
    const float* gxp = g_gx + (size_t)(b0 + bl) * Gsz + j0 + jl;
    const size_t gxstep = (size_t)128 * Gsz;
    float gxr = __ldcg(gxp);
    float gxz = __ldcg(gxp + 256);
    float gxn = __ldcg(gxp + 512);

    const int lrow = lane & 15, lkh = lane >> 4;
    const unsigned aAh = (unsigned)__cvta_generic_to_shared(sAh);
    const unsigned aAl = (unsigned)__cvta_generic_to_shared(sAl);

    int cur = 0;
    for (int t = 0; t < Tsz; ++t) {
        if (t > 0) {
            const unsigned* c = cnt + ((t - 1) << 3) + bg;
            unsigned v;
            do {
                asm volatile("ld.acquire.gpu.global.u32 %0, [%1];"
                             : "=r"(v) : "l"(c) : "memory");
            } while (v < 16u);
        }
        // stage h(t): 16 rows x 256 -> bf16 hi/lo planes (ldmatrix layout)
        const float* hsrc = g_hbuf + cur * (Bsz * Hsz) + (b0 << 8);
#pragma unroll
        for (int r = 0; r < 4; ++r) {
            const int idx = tid + (r << 8);        // 0..1023
            const int row = idx >> 6, f4 = idx & 63;
            float4 v = __ldcg((const float4*)(hsrc + (row << 8)) + f4);
            const int ks = f4 >> 2, pc = (f4 & 3) << 1;
            const int di = ((ks << 4) + row) * AKU + pc;
            float r0, r1, r2, r3;
            sAh[di]     = pack2bf(v.x, v.y, r0, r1);
            sAh[di + 1] = pack2bf(v.z, v.w, r2, r3);
            sAl[di]     = pack2bf_only(r0, r1);
            sAl[di + 1] = pack2bf_only(r2, r3);
        }
        // exact f32 hold tile (one element per thread)
        sHold[bl * 17 + jl] = __ldcg(hsrc + (bl << 8) + j0 + jl);
        __syncthreads();

        // MMA over this warp's k-chunk
        float c[6][4];
#pragma unroll
        for (int ns = 0; ns < 6; ++ns)
#pragma unroll
            for (int i = 0; i < 4; ++i) c[ns][i] = 0.0f;

#pragma unroll
        for (int s = 0; s < 2; ++s) {
            const int ksg = warp * 2 + s;
            const unsigned off =
                ((unsigned)(((ksg << 4) + lrow) * AKU + (lkh << 2))) << 2;
            unsigned Ah[4], Al[4];
            LDSM_X4(Ah[0], Ah[1], Ah[2], Ah[3], aAh + off);
            LDSM_X4(Al[0], Al[1], Al[2], Al[3], aAl + off);
#pragma unroll
            for (int ns = 0; ns < 6; ++ns) MMA_BF16(c[ns], Ah, Bh[s][ns]);
#pragma unroll
            for (int ns = 0; ns < 6; ++ns) MMA_BF16(c[ns], Ah, Bl[s][ns]);
#pragma unroll
            for (int ns = 0; ns < 6; ++ns) MMA_BF16(c[ns], Al, Bh[s][ns]);
        }
        // store fp32 partials
        float* spw = sp + warp * (16 * SP_STRIDE);
#pragma unroll
        for (int ns = 0; ns < 6; ++ns) {
            const int n = ns * 8 + tg * 2;
            spw[gr * SP_STRIDE + n]           = c[ns][0];
            spw[gr * SP_STRIDE + n + 1]       = c[ns][1];
            spw[(gr + 8) * SP_STRIDE + n]     = c[ns][2];
            spw[(gr + 8) * SP_STRIDE + n + 1] = c[ns][3];
        }
        __syncthreads();

        // epilogue: one (b, j) per thread; 8-way k-chunk reduce
        float ar = bhr + gxr, az = bhz + gxz, an = bhn;
#pragma unroll
        for (int w8 = 0; w8 < 8; ++w8) {
            const float* q = sp + w8 * (16 * SP_STRIDE) + bl * SP_STRIDE;
            ar += q[jl];
            az += q[16 + jl];
            an += q[32 + jl];
        }
        const float r = __fdividef(1.0f, 1.0f + __expf(-ar));
        const float z = __fdividef(1.0f, 1.0f + __expf(-az));
        const float xn = fmaf(r, an, gxn);
        const float e = __expf(2.0f * fabsf(xn));
        float n = 1.0f - __fdividef(2.0f, e + 1.0f);
        n = copysignf(n, xn);

        const float hold = sHold[bl * 17 + jl];
        const float hnew = fmaf(z, hold - n, n);   // (1-z)*n + z*h

        __stcg(g_hbuf + (cur ^ 1) * (Bsz * Hsz) + ((b0 + bl) << 8) + j0 + jl, hnew);
        if (write_ys)
            g_h1[(size_t)((t << 7) + b0 + bl) * Hsz + j0 + jl] = hnew;

        if (t + 1 < Tsz) {
            const float* p = gxp + (size_t)(t + 1) * gxstep;
            gxr = __ldcg(p);
            gxz = __ldcg(p + 256);
            gxn = __ldcg(p + 512);
        }

        __syncthreads();   // all smem reads done, hnew stores issued
        if (t + 1 < Tsz && tid == 0) {
            asm volatile("red.release.gpu.global.add.u32 [%0], 1;"
                         :: "l"(cnt + (t << 3) + bg) : "memory");
        }
        cur ^= 1;
    }
}

// ---- head: out[b] = W2 . relu(W1 . h_last[b] + b1) + b2 --------------------
__global__ void head_kernel(const float* __restrict__ W1, const float* __restrict__ b1,
                            const float* __restrict__ W2, const float* __restrict__ b2,
                            float* __restrict__ out)
{
    __shared__ float red[128];
    const int b = blockIdx.x, u = threadIdx.x;
    const float* hb = g_hbuf + (b << 8);
    const float* w  = W1 + (size_t)u * 256;

    float acc = b1[u];
#pragma unroll 8
    for (int k4 = 0; k4 < 64; ++k4) {
        const float4 h4 = __ldcg((const float4*)hb + k4);
        const float4 w4 = __ldg((const float4*)w + k4);
        acc = fmaf(h4.x, w4.x, acc); acc = fmaf(h4.y, w4.y, acc);
        acc = fmaf(h4.z, w4.z, acc); acc = fmaf(h4.w, w4.w, acc);
    }
    red[u] = fmaxf(acc, 0.0f) * __ldg(W2 + u);
    __syncthreads();
#pragma unroll
    for (int s = 64; s > 0; s >>= 1) {
        if (u < s) red[u] += red[u + s];
        __syncthreads();
    }
    if (u == 0) out[b] = red[0] + b2[0];
}

// ---- launch sequence (graph-capturable: kernel launches only) --------------
extern "C" void kernel_launch(void* const* d_in, const int* in_sizes, int n_in,
                              void* d_out, int out_size)
{
    const float* x    = (const float*)d_in[0];
    const float* Wih0 = (const float*)d_in[1];
    const float* Whh0 = (const float*)d_in[2];
    const float* bih0 = (const float*)d_in[3];
    const float* bhh0 = (const float*)d_in[4];
    const float* Wih1 = (const float*)d_in[5];
    const float* Whh1 = (const float*)d_in[6];
    const float* bih1 = (const float*)d_in[7];
    const float* bhh1 = (const float*)d_in[8];
    const float* W1   = (const float*)d_in[9];
    const float* b1   = (const float*)d_in[10];
    const float* W2   = (const float*)d_in[11];
    const float* b2   = (const float*)d_in[12];
    float* out = (float*)d_out;

    cudaFuncSetAttribute(gru_scan_mma, cudaFuncAttributeMaxDynamicSharedMemorySize,
                         SCAN2_BYTES);

    const dim3 ggrid(12, 512);

    // fresh state + barrier counters every replay
    zero_state<<<64, 256>>>(1);

    // layer 0
    gemm_bf16x2<<<ggrid, 256>>>(x, Wih0, bih0, Isz, 0);
    gru_scan_mma<<<128, 256, SCAN2_BYTES>>>(Whh0, bhh0, 0, 1);

    // layer 1 (re-zero hidden state: layer 1 starts from h=0)
    gemm_bf16x2<<<ggrid, 256>>>(x, Wih1, bih1, Hsz, 1);
    zero_state<<<64, 256>>>(0);
    gru_scan_mma<<<128, 256, SCAN2_BYTES>>>(Whh1, bhh1, 1, 0);

    // head
    head_kernel<<<128, 128>>>(W1, b1, W2, b2, out);
}